// round 1
// baseline (speedup 1.0000x reference)
#include <cuda_runtime.h>
#include <cstdint>
#include <cub/cub.cuh>

#define NOFF  27
#define SGRID 1024
#define HBITS 21
#define HSIZE (1u << HBITS)
#define HMASK (HSIZE - 1u)
#define MAXN  400000

// ---- static device scratch (no allocations allowed) ----
__device__ uint32_t g_keys[MAXN];
__device__ uint32_t g_vals[MAXN];
__device__ uint32_t g_skeys[MAXN];
__device__ uint32_t g_order[MAXN];
__device__ int      g_hkey[HSIZE];
__device__ int      g_hval[HSIZE];
__device__ int      g_okeys[NOFF];
__device__ int      g_zidx;
__device__ unsigned char g_temp[16u << 20];   // cub radix-sort arena

// ---------------- pack coordinate keys ----------------
__global__ void k_keys(const int* __restrict__ coords, int n) {
    int i = blockIdx.x * blockDim.x + threadIdx.x;
    if (i < n) {
        int x = coords[3 * i], y = coords[3 * i + 1], z = coords[3 * i + 2];
        g_keys[i] = (uint32_t)((x * SGRID + y) * SGRID + z);
        g_vals[i] = (uint32_t)i;
    }
}

// ---------------- pack offset keys, find center ----------------
__global__ void k_off(const int* __restrict__ offsets) {
    int k = threadIdx.x;
    if (k < NOFF) {
        int ok = (offsets[3 * k] * SGRID + offsets[3 * k + 1]) * SGRID + offsets[3 * k + 2];
        g_okeys[k] = ok;
        if (ok == 0) g_zidx = k;
    }
}

// ---------------- hash table ----------------
__global__ void k_hclear() {
    int i = blockIdx.x * blockDim.x + threadIdx.x;
    if (i < (int)HSIZE) g_hkey[i] = -1;
}

__global__ void k_hash(int n) {
    int i = blockIdx.x * blockDim.x + threadIdx.x;
    if (i < n) {
        int key = (int)g_skeys[i];
        uint32_t h = ((uint32_t)key * 2654435761u) >> (32 - HBITS);
        for (;;) {
            int prev = atomicCAS(&g_hkey[h], -1, key);
            if (prev == -1) { g_hval[h] = i; break; }
            h = (h + 1) & HMASK;
        }
    }
}

__device__ __forceinline__ int hlookup(int qk) {
    uint32_t h = ((uint32_t)qk * 2654435761u) >> (32 - HBITS);
    for (;;) {
        int k = g_hkey[h];
        if (k == qk) return g_hval[h];
        if (k == -1) return -1;
        h = (h + 1) & HMASK;
    }
}

// ---------------- fused gather + dense-center GEMM + sparse corrections ----------------
// block: 256 threads = 16(ty) x 16(tx); tile = 64 rows x 64 cols; thread micro-tile 4x4.
__global__ __launch_bounds__(256) void k_conv(
    const float* __restrict__ feat, const float* __restrict__ W,
    float* __restrict__ out, int n)
{
    __shared__ float    As[64][68];       // gathered A tile, row-major, padded
    __shared__ float    Ws[64][64];       // W_center  [cin][cout]
    __shared__ int      js[NOFF * 64];    // match index per (offset,row), -1 = miss
    __shared__ uint32_t tk[64];           // tile sorted keys
    __shared__ int      s_ok[NOFF];

    const int tid = threadIdx.x;
    const int r0  = blockIdx.x * 64;
    const int zk  = g_zidx;

    if (tid < NOFF) s_ok[tid] = g_okeys[tid];
    if (tid < 64)   tk[tid] = (r0 + tid < n) ? g_skeys[r0 + tid] : 0xFFFFFFFFu;

    // W_center -> smem (contiguous copy, layout [cin][cout] preserved)
    {
        const float4* Wz4 = (const float4*)(W + (size_t)zk * 64 * 64);
        float4* Ws4 = (float4*)&Ws[0][0];
        for (int i = tid; i < 1024; i += 256) Ws4[i] = Wz4[i];
    }

    // gather A tile rows through the sort permutation
    {
        int r = tid >> 2, q = tid & 3;          // 4 threads per row, 16 floats each
        int gr = r0 + r;
        float4* dst = (float4*)&As[r][q * 16];
        if (gr < n) {
            const float4* a4 = (const float4*)(feat + (size_t)g_order[gr] * 64);
            #pragma unroll
            for (int kk = 0; kk < 4; kk++) dst[kk] = a4[q * 4 + kk];
        } else {
            float4 zz = make_float4(0.f, 0.f, 0.f, 0.f);
            #pragma unroll
            for (int kk = 0; kk < 4; kk++) dst[kk] = zz;
        }
    }
    __syncthreads();

    // hash probes for the 26 non-center offsets (27*64 = 1728 probes / block)
    for (int p = tid; p < NOFF * 64; p += 256) {
        int kk = p >> 6, r = p & 63;
        int v = -1;
        if (kk != zk && r0 + r < n) {
            int qk = (int)tk[r] + s_ok[kk];
            v = hlookup(qk);
        }
        js[p] = v;
    }

    // dense center GEMM: acc += A_tile @ W_center
    const int ty = tid >> 4, tx = tid & 15;
    float acc[4][4] = {};
    #pragma unroll 8
    for (int k = 0; k < 64; k++) {
        float a0 = As[ty * 4 + 0][k];
        float a1 = As[ty * 4 + 1][k];
        float a2 = As[ty * 4 + 2][k];
        float a3 = As[ty * 4 + 3][k];
        float4 w = *(const float4*)&Ws[k][tx * 4];
        acc[0][0] += a0 * w.x; acc[0][1] += a0 * w.y; acc[0][2] += a0 * w.z; acc[0][3] += a0 * w.w;
        acc[1][0] += a1 * w.x; acc[1][1] += a1 * w.y; acc[1][2] += a1 * w.z; acc[1][3] += a1 * w.w;
        acc[2][0] += a2 * w.x; acc[2][1] += a2 * w.y; acc[2][2] += a2 * w.z; acc[2][3] += a2 * w.w;
        acc[3][0] += a3 * w.x; acc[3][1] += a3 * w.y; acc[3][2] += a3 * w.z; acc[3][3] += a3 * w.w;
    }
    __syncthreads();   // js fully written before reads

    // sparse corrections (rare-taken: ~1% of rows across all 26 offsets)
    for (int kk = 0; kk < NOFF; kk++) {
        if (kk == zk) continue;
        const float* Wk = W + (size_t)kk * 64 * 64;
        #pragma unroll
        for (int i = 0; i < 4; i++) {
            int j = js[kk * 64 + ty * 4 + i];
            if (j >= 0) {
                const float* arow = feat + (size_t)g_order[j] * 64;
                #pragma unroll 8
                for (int k = 0; k < 64; k++) {
                    float a = __ldg(arow + k);
                    float4 w = __ldg((const float4*)(Wk + k * 64 + tx * 4));
                    acc[i][0] += a * w.x; acc[i][1] += a * w.y;
                    acc[i][2] += a * w.z; acc[i][3] += a * w.w;
                }
            }
        }
    }

    // write output tile (sorted-order rows)
    #pragma unroll
    for (int i = 0; i < 4; i++) {
        int gr = r0 + ty * 4 + i;
        if (gr < n) {
            float4 v = make_float4(acc[i][0], acc[i][1], acc[i][2], acc[i][3]);
            *(float4*)(out + (size_t)gr * 64 + tx * 4) = v;
        }
    }
}

// ---------------- launch ----------------
extern "C" void kernel_launch(void* const* d_in, const int* in_sizes, int n_in,
                              void* d_out, int out_size) {
    const float* feat    = (const float*)d_in[0];
    const float* W       = (const float*)d_in[1];
    const int*   coords  = (const int*)d_in[2];
    const int*   offsets = (const int*)d_in[3];
    float*       out     = (float*)d_out;
    const int n = in_sizes[0] / 64;

    void *p_keys, *p_vals, *p_skeys, *p_order, *p_temp;
    cudaGetSymbolAddress(&p_keys,  g_keys);
    cudaGetSymbolAddress(&p_vals,  g_vals);
    cudaGetSymbolAddress(&p_skeys, g_skeys);
    cudaGetSymbolAddress(&p_order, g_order);
    cudaGetSymbolAddress(&p_temp,  g_temp);

    k_keys<<<(n + 255) / 256, 256>>>(coords, n);
    k_off<<<1, 32>>>(offsets);

    size_t temp_bytes = sizeof(g_temp);
    cub::DeviceRadixSort::SortPairs(p_temp, temp_bytes,
                                    (const uint32_t*)p_keys,  (uint32_t*)p_skeys,
                                    (const uint32_t*)p_vals,  (uint32_t*)p_order,
                                    n, 0, 30);

    k_hclear<<<(HSIZE + 255) / 256, 256>>>();
    k_hash<<<(n + 255) / 256, 256>>>(n);

    k_conv<<<(n + 63) / 64, 256>>>(feat, W, out, n);
}